// round 15
// baseline (speedup 1.0000x reference)
#include <cuda_runtime.h>
#include <math.h>

#define BATCH   4096
#define LIN     4448
#define LP      278
#define L2OUT   139
#define NQ      8
#define SD      256
#define NLAY    3

__device__ float g_feat[BATCH * SD];    // extractor features

// ---------- packed f32x2 helpers ----------
__device__ __forceinline__ unsigned long long splat2(float x) {
    unsigned long long r; unsigned u = __float_as_uint(x);
    asm("mov.b64 %0, {%1, %1};" : "=l"(r) : "r"(u));
    return r;
}
__device__ __forceinline__ unsigned long long fma2(unsigned long long a,
                                                   unsigned long long b,
                                                   unsigned long long c) {
    unsigned long long d;
    asm("fma.rn.f32x2 %0, %1, %2, %3;" : "=l"(d) : "l"(a), "l"(b), "l"(c));
    return d;
}
__device__ __forceinline__ float2 unpack2(unsigned long long v) {
    unsigned lo, hi;
    asm("mov.b64 {%0, %1}, %2;" : "=r"(lo), "=r"(hi) : "l"(v));
    return make_float2(__uint_as_float(lo), __uint_as_float(hi));
}

// ---------------- Kernel 1: conv stack (R14 verbatim, measured 136.3 us) ----------
#define SM_REG   0
#define SM_H2    0
#define SM_POOL  4520
#define PROW     308
#define SM_W1P   (SM_POOL + 16*PROW)
#define SM_W2P   (SM_W1P + 240)
#define SM_BN1S  (SM_W2P + 3584)
#define SM_BN1B  (SM_BN1S + 16)
#define SM_BN2S  (SM_BN1B + 16)
#define SM_BN2B  (SM_BN2S + 32)
#define SM1_TOTAL (SM_BN2B + 32)

__global__ void __launch_bounds__(256, 4) k_conv(
    const float* __restrict__ flux,
    const float* __restrict__ w1, const float* __restrict__ g1, const float* __restrict__ b1,
    const float* __restrict__ w2, const float* __restrict__ g2, const float* __restrict__ b2)
{
    extern __shared__ float sm[];
    const int tid = threadIdx.x;
    const int s = blockIdx.x;

    if (tid < 8) sm[SM_REG + tid] = 0.f;
    if (tid >= 64 && tid < 128) sm[SM_REG + 4392 + tid] = 0.f;
    {
        const float4* fx4 = (const float4*)(flux + (size_t)s * LIN);
        float4* dst = (float4*)(sm + SM_REG + 8);
        for (int i = tid; i < LIN/4; i += 256) dst[i] = fx4[i];
    }
    if (tid < 120) {
        int k = tid / 8, cp = tid % 8;
        sm[SM_W1P + (k*8 + cp)*2 + 0] = w1[cp*15 + k];
        sm[SM_W1P + (k*8 + cp)*2 + 1] = w1[(cp+8)*15 + k];
    }
    for (int i = tid; i < 112*16; i += 256) {
        int ck = i >> 4, cp = i & 15;
        sm[SM_W2P + i*2 + 0] = w2[cp*112 + ck];
        sm[SM_W2P + i*2 + 1] = w2[(cp+16)*112 + ck];
    }
    const float inv_eps = rsqrtf(1.0f + 1e-5f);
    if (tid >= 128 && tid < 144) { sm[SM_BN1S + tid-128] = g1[tid-128] * inv_eps; sm[SM_BN1B + tid-128] = b1[tid-128]; }
    if (tid >= 160 && tid < 192) { sm[SM_BN2S + tid-160] = g2[tid-160] * inv_eps; sm[SM_BN2B + tid-160] = b2[tid-160]; }
    // zero only pool halo [0,3) and tail [281,308) per row
    for (int i = tid; i < 480; i += 256) {
        int r = i / 30, k = i % 30;
        int idx = (k < 3) ? k : (278 + k);
        sm[SM_POOL + r*PROW + idx] = 0.f;
    }
    __syncthreads();

    {
        const int cp = tid & 7, jb = tid >> 3;
        unsigned long long wp[15];
        #pragma unroll
        for (int k = 0; k < 15; k++)
            wp[k] = *(const unsigned long long*)&sm[SM_W1P + (k*8 + cp)*2];
        const float sc0 = sm[SM_BN1S + cp],     bt0 = sm[SM_BN1B + cp];
        const float sc1 = sm[SM_BN1S + cp + 8], bt1 = sm[SM_BN1B + cp + 8];
        for (int j = jb; j < LP; j += 32) {
            const float* fb = sm + SM_REG + 16*j;
            unsigned long long a0 = 0ull, a1 = 0ull, a2 = 0ull, a3 = 0ull;
            #pragma unroll
            for (int t4 = 0; t4 < 7; t4++) {
                float4 fq = *(const float4*)(fb + 4*t4);
                float fe[4] = {fq.x, fq.y, fq.z, fq.w};
                #pragma unroll
                for (int e = 0; e < 4; e++) {
                    int t = 4*t4 + e - 1;
                    if (t < 0 || t > 26) continue;
                    unsigned long long fs = splat2(fe[e]);
                    if (t < 15)            a0 = fma2(wp[t],    fs, a0);
                    if (t >= 4 && t < 19)  a1 = fma2(wp[t-4],  fs, a1);
                    if (t >= 8 && t < 23)  a2 = fma2(wp[t-8],  fs, a2);
                    if (t >= 12)           a3 = fma2(wp[t-12], fs, a3);
                }
            }
            float2 v0 = unpack2(a0), v1 = unpack2(a1), v2 = unpack2(a2), v3 = unpack2(a3);
            float mlo = fmaxf(fmaxf(v0.x, v1.x), fmaxf(v2.x, v3.x));
            float mhi = fmaxf(fmaxf(v0.y, v1.y), fmaxf(v2.y, v3.y));
            sm[SM_POOL + cp*PROW + 3 + j]     = fmaxf(mlo*sc0 + bt0, 0.f);
            sm[SM_POOL + (cp+8)*PROW + 3 + j] = fmaxf(mhi*sc1 + bt1, 0.f);
        }
    }
    __syncthreads();

    {
        const int cp = tid & 15, pg = tid >> 4;
        const float sc0 = sm[SM_BN2S + cp],      bt0 = sm[SM_BN2B + cp];
        const float sc1 = sm[SM_BN2S + cp + 16], bt1 = sm[SM_BN2B + cp + 16];
        const int p0 = pg * 9;
        unsigned long long acc[9];
        #pragma unroll
        for (int i = 0; i < 9; i++) acc[i] = 0ull;
        #pragma unroll
        for (int c = 0; c < 16; c++) {
            unsigned long long wp[7];
            #pragma unroll
            for (int k = 0; k < 7; k++)
                wp[k] = *(const unsigned long long*)&sm[SM_W2P + ((c*7 + k)*16 + cp)*2];
            const float* frow = sm + SM_POOL + c*PROW + 2*p0;
            #pragma unroll
            for (int t2 = 0; t2 < 12; t2++) {
                float2 fd = *(const float2*)(frow + 2*t2);
                float fe[2] = {fd.x, fd.y};
                #pragma unroll
                for (int e = 0; e < 2; e++) {
                    int t = 2*t2 + e;
                    if (t > 22) continue;
                    unsigned long long fs = splat2(fe[e]);
                    #pragma unroll
                    for (int i = 0; i < 9; i++) {
                        int k = t - 2*i;
                        if (k >= 0 && k < 7) acc[i] = fma2(wp[k], fs, acc[i]);
                    }
                }
            }
        }
        #pragma unroll
        for (int i = 0; i < 9; i++) {
            if (p0 + i < L2OUT) {
                float2 v = unpack2(acc[i]);
                sm[SM_H2 + cp*141 + p0 + i]      = fmaxf(v.x*sc0 + bt0, 0.f);
                sm[SM_H2 + (cp+16)*141 + p0 + i] = fmaxf(v.y*sc1 + bt1, 0.f);
            }
        }
    }
    __syncthreads();

    {
        const int c = tid >> 3, i = tid & 7;
        const int st = (i * L2OUT) >> 3;
        const int en = ((i + 1) * L2OUT + 7) >> 3;
        float acc = 0.f;
        for (int p = st; p < en; p++) acc += sm[SM_H2 + c*141 + p];
        g_feat[(size_t)s * SD + c*8 + i] = acc / (float)(en - st);
    }
}

// ---------------- Kernel 2: proj + normalize + VQC + head (merged) ----------------
#define TB 16
#define PW1 260                          // W1 row stride (staged)
#define PW2 68                           // W2 row stride (staged, same region)
#define PPAIR 524                        // feat sample-pair row stride
#define PX 264                           // per-sample state row stride
#define PY 132                           // y1 pair row stride
#define S2_A 0                           // max(64*260, 256*68) = 17408
#define S2_B 17408                       // feats 8*524=4192 OR x 16*264=4224 (overlay)
#define S2_C (S2_B + 16*PX)              // y1: 8*132 = 1056
#define S2_R (S2_C + 8*PY)               // rot: 24*8 = 192
#define SM2_TOTAL (S2_R + 192)           // 22880 floats = 91520 B -> 2 blocks/SM

__global__ __launch_bounds__(512) void k_tail(
    const float* __restrict__ scalars,
    const float* __restrict__ W1, const float* __restrict__ B1,
    const float* __restrict__ W2, const float* __restrict__ B2,
    const float* __restrict__ qw,
    const float* __restrict__ hw1, const float* __restrict__ hb1,
    const float* __restrict__ hg,  const float* __restrict__ hbb,
    const float* __restrict__ hw2, const float* __restrict__ hb2,
    float* __restrict__ out)
{
    extern __shared__ float sm[];
    const int tid = threadIdx.x;
    const int s0 = blockIdx.x * TB;

    // rot matrices (computed once per block)
    if (tid < NLAY*NQ) {
        float phi = __ldg(qw + tid*3 + 0);
        float th  = __ldg(qw + tid*3 + 1);
        float om  = __ldg(qw + tid*3 + 2);
        float sh, ch; sincosf(0.5f*th, &sh, &ch);
        float sa, ca; sincosf(0.5f*(phi + om), &sa, &ca);
        float sb, cb; sincosf(0.5f*(phi - om), &sb, &cb);
        float* u = sm + S2_R + tid*8;
        u[0] =  ca*ch;  u[1] = -sa*ch;
        u[2] = -cb*sh;  u[3] = -sb*sh;
        u[4] =  cb*sh;  u[5] = -sb*sh;
        u[6] =  ca*ch;  u[7] =  sa*ch;
    }
    // stage W1 [64][256] -> rows stride 260
    {
        const float4* w4 = (const float4*)W1;
        for (int i4 = tid; i4 < 4096; i4 += 512) {
            int row = i4 >> 6, col = i4 & 63;
            *(float4*)&sm[S2_A + row*PW1 + col*4] = __ldg(w4 + i4);
        }
    }
    // stage feats sample-pair interleaved
    {
        const int pr = tid >> 6, k4 = tid & 63;
        const float4* fa = (const float4*)(g_feat + (size_t)(s0 + 2*pr)*SD);
        const float4* fb = (const float4*)(g_feat + (size_t)(s0 + 2*pr + 1)*SD);
        float4 a = __ldg(fa + k4), b = __ldg(fb + k4);
        float* dst = sm + S2_B + pr*PPAIR + k4*8;
        *(float4*)(dst)     = make_float4(a.x, b.x, a.y, b.y);
        *(float4*)(dst + 4) = make_float4(a.z, b.z, a.w, b.w);
    }
    __syncthreads();

    // proj1: thread = (j, pair sg); packed f32x2, k-ascending
    {
        const int j = tid >> 3, sg = tid & 7;
        unsigned long long acc = splat2(__ldg(B1 + j));
        const float* wrow = sm + S2_A + j*PW1;
        const float* prow = sm + S2_B + sg*PPAIR;
        #pragma unroll 8
        for (int it = 0; it < 64; it++) {
            float4 w = *(const float4*)(wrow + 4*it);
            unsigned long long p0 = *(const unsigned long long*)(prow + 8*it);
            unsigned long long p1 = *(const unsigned long long*)(prow + 8*it + 2);
            unsigned long long p2 = *(const unsigned long long*)(prow + 8*it + 4);
            unsigned long long p3 = *(const unsigned long long*)(prow + 8*it + 6);
            acc = fma2(splat2(w.x), p0, acc);
            acc = fma2(splat2(w.y), p1, acc);
            acc = fma2(splat2(w.z), p2, acc);
            acc = fma2(splat2(w.w), p3, acc);
        }
        float2 v = unpack2(acc);
        *(float2*)&sm[S2_C + sg*PY + 2*j] = make_float2(fmaxf(v.x, 0.f), fmaxf(v.y, 0.f));
    }
    __syncthreads();
    // stage W2 [256][64] -> rows stride 68 (overwrites W1 region)
    {
        const float4* w4 = (const float4*)W2;
        for (int i4 = tid; i4 < 4096; i4 += 512) {
            int row = i4 >> 4, col = i4 & 15;
            *(float4*)&sm[S2_A + row*PW2 + col*4] = __ldg(w4 + i4);
        }
    }
    __syncthreads();

    // proj2: thread = (m, 8-sample group); writes states to smem (overlays feats)
    {
        const int m = tid & 255, sg = tid >> 8;
        const float bb = __ldg(B2 + m);
        unsigned long long acc2[4];
        #pragma unroll
        for (int p = 0; p < 4; p++) acc2[p] = splat2(bb);
        const float* wrow = sm + S2_A + m*PW2;
        #pragma unroll 4
        for (int it = 0; it < 16; it++) {
            float4 w = *(const float4*)(wrow + 4*it);
            unsigned long long wx = splat2(w.x), wy = splat2(w.y);
            unsigned long long wz = splat2(w.z), ww = splat2(w.w);
            #pragma unroll
            for (int p = 0; p < 4; p++) {
                const float* yrow = sm + S2_C + (sg*4 + p)*PY + 8*it;
                unsigned long long q0 = *(const unsigned long long*)(yrow);
                unsigned long long q1 = *(const unsigned long long*)(yrow + 2);
                unsigned long long q2 = *(const unsigned long long*)(yrow + 4);
                unsigned long long q3 = *(const unsigned long long*)(yrow + 6);
                acc2[p] = fma2(wx, q0, acc2[p]);
                acc2[p] = fma2(wy, q1, acc2[p]);
                acc2[p] = fma2(wz, q2, acc2[p]);
                acc2[p] = fma2(ww, q3, acc2[p]);
            }
        }
        #pragma unroll
        for (int p = 0; p < 4; p++) {
            float2 v = unpack2(acc2[p]);
            sm[S2_B + (sg*8 + 2*p)*PX + m]     = v.x;
            sm[S2_B + (sg*8 + 2*p + 1)*PX + m] = v.y;
        }
    }
    __syncthreads();

    // one warp per sample: normalize + circuit + head
    const int warp = tid >> 5, lane = tid & 31;
    const unsigned FULL = 0xffffffffu;
    const int gs = s0 + warp;

    float are[8], aim[8];
    {
        const float* xr = sm + S2_B + warp*PX + lane*8;
        float4 v0 = *(const float4*)(xr);
        float4 v1 = *(const float4*)(xr + 4);
        are[0] = v0.x; are[1] = v0.y; are[2] = v0.z; are[3] = v0.w;
        are[4] = v1.x; are[5] = v1.y; are[6] = v1.z; are[7] = v1.w;
    }
    float sq = 0.f;
    #pragma unroll
    for (int m = 0; m < 8; m++) { aim[m] = 0.f; sq += are[m]*are[m]; }
    #pragma unroll
    for (int off = 16; off; off >>= 1) sq += __shfl_xor_sync(FULL, sq, off);
    float n   = sqrtf(sq);
    float inv = 1.0f / fmaxf(n, 1e-12f);
    if (n * inv < 1e-8f) {
        #pragma unroll
        for (int m = 0; m < 8; m++) are[m] = 0.0625f;
    } else {
        #pragma unroll
        for (int m = 0; m < 8; m++) are[m] *= inv;
    }

    for (int l = 0; l < NLAY; l++) {
        for (int q = 0; q < NQ; q++) {
            const float* u = sm + S2_R + (l*NQ + q)*8;
            float u00r = u[0], u00i = u[1], u01r = u[2], u01i = u[3];
            float u10r = u[4], u10i = u[5], u11r = u[6], u11i = u[7];
            int b = 7 - q;
            if (b >= 3) {
                int lb = b - 3;
                unsigned msk = 1u << lb;
                bool hi = (lane >> lb) & 1;
                float r0 = hi ? u10r : u00r, i0 = hi ? u10i : u00i;
                float r1 = hi ? u11r : u01r, i1 = hi ? u11i : u01i;
                #pragma unroll
                for (int m = 0; m < 8; m++) {
                    float pr = __shfl_xor_sync(FULL, are[m], msk);
                    float pi = __shfl_xor_sync(FULL, aim[m], msk);
                    float a0r = hi ? pr : are[m], a0i = hi ? pi : aim[m];
                    float a1r = hi ? are[m] : pr, a1i = hi ? aim[m] : pi;
                    are[m] = r0*a0r - i0*a0i + r1*a1r - i1*a1i;
                    aim[m] = r0*a0i + i0*a0r + r1*a1i + i1*a1r;
                }
            } else {
                int mb = 1 << b;
                #pragma unroll
                for (int m0 = 0; m0 < 8; m0++) {
                    if (m0 & mb) continue;
                    int m1 = m0 | mb;
                    float a0r = are[m0], a0i = aim[m0];
                    float a1r = are[m1], a1i = aim[m1];
                    are[m0] = u00r*a0r - u00i*a0i + u01r*a1r - u01i*a1i;
                    aim[m0] = u00r*a0i + u00i*a0r + u01r*a1i + u01i*a1r;
                    are[m1] = u10r*a0r - u10i*a0i + u11r*a1r - u11i*a1i;
                    aim[m1] = u10r*a0i + u10i*a0r + u11r*a1i + u11i*a1r;
                }
            }
        }
        #pragma unroll
        for (int q = 0; q < 4; q++) {
            unsigned shm  = 1u << (3 - q);
            unsigned cond = 1u << (4 - q);
            bool take = (lane & cond) != 0;
            #pragma unroll
            for (int m = 0; m < 8; m++) {
                float pr = __shfl_xor_sync(FULL, are[m], shm);
                float pi = __shfl_xor_sync(FULL, aim[m], shm);
                if (take) { are[m] = pr; aim[m] = pi; }
            }
        }
        if (lane & 1) {
            #pragma unroll
            for (int m = 0; m < 4; m++) {
                float tr = are[m]; are[m] = are[m+4]; are[m+4] = tr;
                float ti = aim[m]; aim[m] = aim[m+4]; aim[m+4] = ti;
            }
        }
        {
            float t;
            t = are[4]; are[4] = are[6]; are[6] = t;  t = aim[4]; aim[4] = aim[6]; aim[6] = t;
            t = are[5]; are[5] = are[7]; are[7] = t;  t = aim[5]; aim[5] = aim[7]; aim[7] = t;
            t = are[2]; are[2] = are[3]; are[3] = t;  t = aim[2]; aim[2] = aim[3]; aim[3] = t;
            t = are[6]; are[6] = are[7]; are[7] = t;  t = aim[6]; aim[6] = aim[7]; aim[7] = t;
        }
        #pragma unroll
        for (int m = 1; m < 8; m += 2) {
            are[m] = __shfl_xor_sync(FULL, are[m], 16);
            aim[m] = __shfl_xor_sync(FULL, aim[m], 16);
        }
    }

    float S = 0.f, S5 = 0.f, S6 = 0.f, S7 = 0.f;
    #pragma unroll
    for (int m = 0; m < 8; m++) {
        float p = are[m]*are[m] + aim[m]*aim[m];
        S  += p;
        S5 += (m & 4) ? -p : p;
        S6 += (m & 2) ? -p : p;
        S7 += (m & 1) ? -p : p;
    }
    float z[8];
    z[0] = (lane & 16) ? -S : S;
    z[1] = (lane &  8) ? -S : S;
    z[2] = (lane &  4) ? -S : S;
    z[3] = (lane &  2) ? -S : S;
    z[4] = (lane &  1) ? -S : S;
    z[5] = S5; z[6] = S6; z[7] = S7;
    #pragma unroll
    for (int q = 0; q < 8; q++)
        #pragma unroll
        for (int off = 16; off; off >>= 1)
            z[q] += __shfl_xor_sync(FULL, z[q], off);

    float in[14];
    #pragma unroll
    for (int k = 0; k < 8; k++) in[k] = z[k];
    #pragma unroll
    for (int k = 0; k < 6; k++) in[8 + k] = __ldg(scalars + (size_t)gs*6 + k);
    float acc = __ldg(hb1 + lane);
    #pragma unroll
    for (int k = 0; k < 14; k++) acc += in[k] * __ldg(hw1 + lane*14 + k);
    float bsc = __ldg(hg + lane) * rsqrtf(1.0f + 1e-5f);
    float h = fmaxf(acc*bsc + __ldg(hbb + lane), 0.f);
    #pragma unroll
    for (int o = 0; o < 3; o++) {
        float v = h * __ldg(hw2 + o*32 + lane);
        #pragma unroll
        for (int off = 16; off; off >>= 1) v += __shfl_xor_sync(FULL, v, off);
        if (lane == o) out[(size_t)gs*3 + o] = v + __ldg(hb2 + o);
    }
}

extern "C" void kernel_launch(void* const* d_in, const int* in_sizes, int n_in,
                              void* d_out, int out_size)
{
    const float* flux    = (const float*)d_in[0];
    const float* scalars = (const float*)d_in[1];
    const float* conv1_w = (const float*)d_in[2];
    const float* bn1_g   = (const float*)d_in[3];
    const float* bn1_b   = (const float*)d_in[4];
    const float* conv2_w = (const float*)d_in[5];
    const float* bn2_g   = (const float*)d_in[6];
    const float* bn2_b   = (const float*)d_in[7];
    const float* proj_w1 = (const float*)d_in[8];
    const float* proj_b1 = (const float*)d_in[9];
    const float* proj_w2 = (const float*)d_in[10];
    const float* proj_b2 = (const float*)d_in[11];
    const float* q_w     = (const float*)d_in[12];
    const float* head_w1 = (const float*)d_in[13];
    const float* head_b1 = (const float*)d_in[14];
    const float* head_g  = (const float*)d_in[15];
    const float* head_bb = (const float*)d_in[16];
    const float* head_w2 = (const float*)d_in[17];
    const float* head_b2 = (const float*)d_in[18];
    float* out = (float*)d_out;

    int B = in_sizes[1] / 6;           // scalars [B,6]
    if (B > BATCH) B = BATCH;

    cudaFuncSetAttribute(k_conv, cudaFuncAttributeMaxDynamicSharedMemorySize, SM1_TOTAL*4);
    cudaFuncSetAttribute(k_tail, cudaFuncAttributeMaxDynamicSharedMemorySize, SM2_TOTAL*4);

    k_conv<<<B, 256, SM1_TOTAL*4>>>(flux, conv1_w, bn1_g, bn1_b, conv2_w, bn2_g, bn2_b);
    k_tail<<<B/TB, 512, SM2_TOTAL*4>>>(scalars, proj_w1, proj_b1, proj_w2, proj_b2,
                                       q_w, head_w1, head_b1, head_g, head_bb,
                                       head_w2, head_b2, out);
}

// round 16
// speedup vs baseline: 1.5613x; 1.5613x over previous
#include <cuda_runtime.h>
#include <math.h>

#define BATCH   4096
#define LIN     4448
#define LP      278
#define L2OUT   139
#define NQ      8
#define SD      256
#define NLAY    3

__device__ float g_feat[BATCH * SD];    // extractor features
__device__ float g_state[BATCH * SD];   // pre-circuit states

// ---------- packed f32x2 helpers ----------
__device__ __forceinline__ unsigned long long splat2(float x) {
    unsigned long long r; unsigned u = __float_as_uint(x);
    asm("mov.b64 %0, {%1, %1};" : "=l"(r) : "r"(u));
    return r;
}
__device__ __forceinline__ unsigned long long fma2(unsigned long long a,
                                                   unsigned long long b,
                                                   unsigned long long c) {
    unsigned long long d;
    asm("fma.rn.f32x2 %0, %1, %2, %3;" : "=l"(d) : "l"(a), "l"(b), "l"(c));
    return d;
}
__device__ __forceinline__ float2 unpack2(unsigned long long v) {
    unsigned lo, hi;
    asm("mov.b64 {%0, %1}, %2;" : "=r"(lo), "=r"(hi) : "l"(v));
    return make_float2(__uint_as_float(lo), __uint_as_float(hi));
}

// ---------------- Kernel 1: conv stack (R14 verbatim, measured 136.3 us) ----------
#define SM_REG   0
#define SM_H2    0
#define SM_POOL  4520
#define PROW     308
#define SM_W1P   (SM_POOL + 16*PROW)
#define SM_W2P   (SM_W1P + 240)
#define SM_BN1S  (SM_W2P + 3584)
#define SM_BN1B  (SM_BN1S + 16)
#define SM_BN2S  (SM_BN1B + 16)
#define SM_BN2B  (SM_BN2S + 32)
#define SM1_TOTAL (SM_BN2B + 32)

__global__ void __launch_bounds__(256, 4) k_conv(
    const float* __restrict__ flux,
    const float* __restrict__ w1, const float* __restrict__ g1, const float* __restrict__ b1,
    const float* __restrict__ w2, const float* __restrict__ g2, const float* __restrict__ b2)
{
    extern __shared__ float sm[];
    const int tid = threadIdx.x;
    const int s = blockIdx.x;

    if (tid < 8) sm[SM_REG + tid] = 0.f;
    if (tid >= 64 && tid < 128) sm[SM_REG + 4392 + tid] = 0.f;
    {
        const float4* fx4 = (const float4*)(flux + (size_t)s * LIN);
        float4* dst = (float4*)(sm + SM_REG + 8);
        for (int i = tid; i < LIN/4; i += 256) dst[i] = fx4[i];
    }
    if (tid < 120) {
        int k = tid / 8, cp = tid % 8;
        sm[SM_W1P + (k*8 + cp)*2 + 0] = w1[cp*15 + k];
        sm[SM_W1P + (k*8 + cp)*2 + 1] = w1[(cp+8)*15 + k];
    }
    for (int i = tid; i < 112*16; i += 256) {
        int ck = i >> 4, cp = i & 15;
        sm[SM_W2P + i*2 + 0] = w2[cp*112 + ck];
        sm[SM_W2P + i*2 + 1] = w2[(cp+16)*112 + ck];
    }
    const float inv_eps = rsqrtf(1.0f + 1e-5f);
    if (tid >= 128 && tid < 144) { sm[SM_BN1S + tid-128] = g1[tid-128] * inv_eps; sm[SM_BN1B + tid-128] = b1[tid-128]; }
    if (tid >= 160 && tid < 192) { sm[SM_BN2S + tid-160] = g2[tid-160] * inv_eps; sm[SM_BN2B + tid-160] = b2[tid-160]; }
    // zero only pool halo [0,3) and tail [281,308) per row
    for (int i = tid; i < 480; i += 256) {
        int r = i / 30, k = i % 30;
        int idx = (k < 3) ? k : (278 + k);
        sm[SM_POOL + r*PROW + idx] = 0.f;
    }
    __syncthreads();

    // conv1 (k=15,s=4,p=7) + BN + ReLU + MaxPool4, 2 channels packed; LDS.128 loads
    {
        const int cp = tid & 7, jb = tid >> 3;
        unsigned long long wp[15];
        #pragma unroll
        for (int k = 0; k < 15; k++)
            wp[k] = *(const unsigned long long*)&sm[SM_W1P + (k*8 + cp)*2];
        const float sc0 = sm[SM_BN1S + cp],     bt0 = sm[SM_BN1B + cp];
        const float sc1 = sm[SM_BN1S + cp + 8], bt1 = sm[SM_BN1B + cp + 8];
        for (int j = jb; j < LP; j += 32) {
            const float* fb = sm + SM_REG + 16*j;
            unsigned long long a0 = 0ull, a1 = 0ull, a2 = 0ull, a3 = 0ull;
            #pragma unroll
            for (int t4 = 0; t4 < 7; t4++) {
                float4 fq = *(const float4*)(fb + 4*t4);
                float fe[4] = {fq.x, fq.y, fq.z, fq.w};
                #pragma unroll
                for (int e = 0; e < 4; e++) {
                    int t = 4*t4 + e - 1;
                    if (t < 0 || t > 26) continue;
                    unsigned long long fs = splat2(fe[e]);
                    if (t < 15)            a0 = fma2(wp[t],    fs, a0);
                    if (t >= 4 && t < 19)  a1 = fma2(wp[t-4],  fs, a1);
                    if (t >= 8 && t < 23)  a2 = fma2(wp[t-8],  fs, a2);
                    if (t >= 12)           a3 = fma2(wp[t-12], fs, a3);
                }
            }
            float2 v0 = unpack2(a0), v1 = unpack2(a1), v2 = unpack2(a2), v3 = unpack2(a3);
            float mlo = fmaxf(fmaxf(v0.x, v1.x), fmaxf(v2.x, v3.x));
            float mhi = fmaxf(fmaxf(v0.y, v1.y), fmaxf(v2.y, v3.y));
            sm[SM_POOL + cp*PROW + 3 + j]     = fmaxf(mlo*sc0 + bt0, 0.f);
            sm[SM_POOL + (cp+8)*PROW + 3 + j] = fmaxf(mhi*sc1 + bt1, 0.f);
        }
    }
    __syncthreads();

    // conv2 (16->32, k=7, s=2, p=3) + BN + ReLU; 2 out-ch packed x 9 positions
    {
        const int cp = tid & 15, pg = tid >> 4;
        const float sc0 = sm[SM_BN2S + cp],      bt0 = sm[SM_BN2B + cp];
        const float sc1 = sm[SM_BN2S + cp + 16], bt1 = sm[SM_BN2B + cp + 16];
        const int p0 = pg * 9;
        unsigned long long acc[9];
        #pragma unroll
        for (int i = 0; i < 9; i++) acc[i] = 0ull;
        #pragma unroll
        for (int c = 0; c < 16; c++) {
            unsigned long long wp[7];
            #pragma unroll
            for (int k = 0; k < 7; k++)
                wp[k] = *(const unsigned long long*)&sm[SM_W2P + ((c*7 + k)*16 + cp)*2];
            const float* frow = sm + SM_POOL + c*PROW + 2*p0;
            #pragma unroll
            for (int t2 = 0; t2 < 12; t2++) {
                float2 fd = *(const float2*)(frow + 2*t2);
                float fe[2] = {fd.x, fd.y};
                #pragma unroll
                for (int e = 0; e < 2; e++) {
                    int t = 2*t2 + e;
                    if (t > 22) continue;
                    unsigned long long fs = splat2(fe[e]);
                    #pragma unroll
                    for (int i = 0; i < 9; i++) {
                        int k = t - 2*i;
                        if (k >= 0 && k < 7) acc[i] = fma2(wp[k], fs, acc[i]);
                    }
                }
            }
        }
        #pragma unroll
        for (int i = 0; i < 9; i++) {
            if (p0 + i < L2OUT) {
                float2 v = unpack2(acc[i]);
                sm[SM_H2 + cp*141 + p0 + i]      = fmaxf(v.x*sc0 + bt0, 0.f);
                sm[SM_H2 + (cp+16)*141 + p0 + i] = fmaxf(v.y*sc1 + bt1, 0.f);
            }
        }
    }
    __syncthreads();

    // adaptive_avg_pool1d(139 -> 8), feature layout c*8+i
    {
        const int c = tid >> 3, i = tid & 7;
        const int st = (i * L2OUT) >> 3;
        const int en = ((i + 1) * L2OUT + 7) >> 3;
        float acc = 0.f;
        for (int p = st; p < en; p++) acc += sm[SM_H2 + c*141 + p];
        g_feat[(size_t)s * SD + c*8 + i] = acc / (float)(en - st);
    }
}

// ---------------- Kernel 2: proj (R13 verbatim — W1 staged, packed f32x2) ---------
#define TB 16
#define PW1 260                          // W1 row stride
#define PW2 68                           // W2 row stride
#define PPAIR 524                        // interleaved sample-pair row stride
#define PY 132                           // y1 pair row stride
#define S2_A 0                           // max(64*260, 256*68) = 17408
#define S2_B 17408                       // 8 * 524
#define S2_C (S2_B + 8*PPAIR)            // 8 * 132
#define SM2_TOTAL (S2_C + 8*PY)          // 22656 floats = 90624 B

__global__ __launch_bounds__(512) void k_proj(
    const float* __restrict__ W1, const float* __restrict__ B1,
    const float* __restrict__ W2, const float* __restrict__ B2)
{
    extern __shared__ float sm[];
    const int tid = threadIdx.x;
    const int s0 = blockIdx.x * TB;

    // stage W1 [64][256] -> rows of stride 260, float4
    {
        const float4* w4 = (const float4*)W1;
        for (int i4 = tid; i4 < 4096; i4 += 512) {
            int row = i4 >> 6, col = i4 & 63;
            *(float4*)&sm[S2_A + row*PW1 + col*4] = __ldg(w4 + i4);
        }
    }
    // stage feats sample-pair interleaved: row pr holds {f_{2pr}[k], f_{2pr+1}[k]}
    {
        const int pr = tid >> 6, k4 = tid & 63;
        const float4* fa = (const float4*)(g_feat + (size_t)(s0 + 2*pr)*SD);
        const float4* fb = (const float4*)(g_feat + (size_t)(s0 + 2*pr + 1)*SD);
        float4 a = __ldg(fa + k4), b = __ldg(fb + k4);
        float* dst = sm + S2_B + pr*PPAIR + k4*8;
        *(float4*)(dst)     = make_float4(a.x, b.x, a.y, b.y);
        *(float4*)(dst + 4) = make_float4(a.z, b.z, a.w, b.w);
    }
    __syncthreads();

    // proj1: thread = (j, pair sg); packed f32x2 accumulation, k-ascending
    {
        const int j = tid >> 3, sg = tid & 7;
        unsigned long long acc = splat2(__ldg(B1 + j));
        const float* wrow = sm + S2_A + j*PW1;
        const float* prow = sm + S2_B + sg*PPAIR;
        #pragma unroll 8
        for (int it = 0; it < 64; it++) {
            float4 w = *(const float4*)(wrow + 4*it);
            unsigned long long p0 = *(const unsigned long long*)(prow + 8*it);
            unsigned long long p1 = *(const unsigned long long*)(prow + 8*it + 2);
            unsigned long long p2 = *(const unsigned long long*)(prow + 8*it + 4);
            unsigned long long p3 = *(const unsigned long long*)(prow + 8*it + 6);
            acc = fma2(splat2(w.x), p0, acc);
            acc = fma2(splat2(w.y), p1, acc);
            acc = fma2(splat2(w.z), p2, acc);
            acc = fma2(splat2(w.w), p3, acc);
        }
        float2 v = unpack2(acc);
        *(float2*)&sm[S2_C + sg*PY + 2*j] = make_float2(fmaxf(v.x, 0.f), fmaxf(v.y, 0.f));
    }
    __syncthreads();
    // stage W2 [256][64] -> rows of stride 68 (overwrites W1 region)
    {
        const float4* w4 = (const float4*)W2;
        for (int i4 = tid; i4 < 4096; i4 += 512) {
            int row = i4 >> 4, col = i4 & 15;
            *(float4*)&sm[S2_A + row*PW2 + col*4] = __ldg(w4 + i4);
        }
    }
    __syncthreads();

    // proj2: thread = (m, 8-sample group); 4 packed pair accumulators, j-ascending
    {
        const int m = tid & 255, sg = tid >> 8;
        const float bb = __ldg(B2 + m);
        unsigned long long acc2[4];
        #pragma unroll
        for (int p = 0; p < 4; p++) acc2[p] = splat2(bb);
        const float* wrow = sm + S2_A + m*PW2;
        #pragma unroll 4
        for (int it = 0; it < 16; it++) {
            float4 w = *(const float4*)(wrow + 4*it);
            unsigned long long wx = splat2(w.x), wy = splat2(w.y);
            unsigned long long wz = splat2(w.z), ww = splat2(w.w);
            #pragma unroll
            for (int p = 0; p < 4; p++) {
                const float* yrow = sm + S2_C + (sg*4 + p)*PY + 8*it;
                unsigned long long q0 = *(const unsigned long long*)(yrow);
                unsigned long long q1 = *(const unsigned long long*)(yrow + 2);
                unsigned long long q2 = *(const unsigned long long*)(yrow + 4);
                unsigned long long q3 = *(const unsigned long long*)(yrow + 6);
                acc2[p] = fma2(wx, q0, acc2[p]);
                acc2[p] = fma2(wy, q1, acc2[p]);
                acc2[p] = fma2(wz, q2, acc2[p]);
                acc2[p] = fma2(ww, q3, acc2[p]);
            }
        }
        #pragma unroll
        for (int p = 0; p < 4; p++) {
            float2 v = unpack2(acc2[p]);
            g_state[(size_t)(s0 + sg*8 + 2*p)*SD + m]     = v.x;
            g_state[(size_t)(s0 + sg*8 + 2*p + 1)*SD + m] = v.y;
        }
    }
}

// ---------------- Kernel 3: normalize + VQC + head (R11 verbatim) ----------------
__global__ __launch_bounds__(256) void k_circ(
    const float* __restrict__ scalars,
    const float* __restrict__ qw,
    const float* __restrict__ hw1, const float* __restrict__ hb1,
    const float* __restrict__ hg,  const float* __restrict__ hbb,
    const float* __restrict__ hw2, const float* __restrict__ hb2,
    float* __restrict__ out)
{
    __shared__ float rot[NLAY*NQ*8];
    const int tid = threadIdx.x;

    if (tid < NLAY*NQ) {
        float phi = __ldg(qw + tid*3 + 0);
        float th  = __ldg(qw + tid*3 + 1);
        float om  = __ldg(qw + tid*3 + 2);
        float sh, ch; sincosf(0.5f*th, &sh, &ch);
        float sa, ca; sincosf(0.5f*(phi + om), &sa, &ca);
        float sb, cb; sincosf(0.5f*(phi - om), &sb, &cb);
        float* u = rot + tid*8;
        u[0] =  ca*ch;  u[1] = -sa*ch;
        u[2] = -cb*sh;  u[3] = -sb*sh;
        u[4] =  cb*sh;  u[5] = -sb*sh;
        u[6] =  ca*ch;  u[7] =  sa*ch;
    }
    __syncthreads();

    const int warp = tid >> 5, lane = tid & 31;
    const unsigned FULL = 0xffffffffu;
    const int gs = blockIdx.x * 8 + warp;

    float are[8], aim[8];
    {
        const float4* xr = (const float4*)(g_state + (size_t)gs*SD + lane*8);
        float4 v0 = __ldg(xr), v1 = __ldg(xr + 1);
        are[0] = v0.x; are[1] = v0.y; are[2] = v0.z; are[3] = v0.w;
        are[4] = v1.x; are[5] = v1.y; are[6] = v1.z; are[7] = v1.w;
    }
    float sq = 0.f;
    #pragma unroll
    for (int m = 0; m < 8; m++) { aim[m] = 0.f; sq += are[m]*are[m]; }
    #pragma unroll
    for (int off = 16; off; off >>= 1) sq += __shfl_xor_sync(FULL, sq, off);
    float n   = sqrtf(sq);
    float inv = 1.0f / fmaxf(n, 1e-12f);
    if (n * inv < 1e-8f) {
        #pragma unroll
        for (int m = 0; m < 8; m++) are[m] = 0.0625f;
    } else {
        #pragma unroll
        for (int m = 0; m < 8; m++) are[m] *= inv;
    }

    for (int l = 0; l < NLAY; l++) {
        for (int q = 0; q < NQ; q++) {
            const float* u = rot + (l*NQ + q)*8;
            float u00r = u[0], u00i = u[1], u01r = u[2], u01i = u[3];
            float u10r = u[4], u10i = u[5], u11r = u[6], u11i = u[7];
            int b = 7 - q;
            if (b >= 3) {
                int lb = b - 3;
                unsigned msk = 1u << lb;
                bool hi = (lane >> lb) & 1;
                float r0 = hi ? u10r : u00r, i0 = hi ? u10i : u00i;
                float r1 = hi ? u11r : u01r, i1 = hi ? u11i : u01i;
                #pragma unroll
                for (int m = 0; m < 8; m++) {
                    float pr = __shfl_xor_sync(FULL, are[m], msk);
                    float pi = __shfl_xor_sync(FULL, aim[m], msk);
                    float a0r = hi ? pr : are[m], a0i = hi ? pi : aim[m];
                    float a1r = hi ? are[m] : pr, a1i = hi ? aim[m] : pi;
                    are[m] = r0*a0r - i0*a0i + r1*a1r - i1*a1i;
                    aim[m] = r0*a0i + i0*a0r + r1*a1i + i1*a1r;
                }
            } else {
                int mb = 1 << b;
                #pragma unroll
                for (int m0 = 0; m0 < 8; m0++) {
                    if (m0 & mb) continue;
                    int m1 = m0 | mb;
                    float a0r = are[m0], a0i = aim[m0];
                    float a1r = are[m1], a1i = aim[m1];
                    are[m0] = u00r*a0r - u00i*a0i + u01r*a1r - u01i*a1i;
                    aim[m0] = u00r*a0i + u00i*a0r + u01r*a1i + u01i*a1r;
                    are[m1] = u10r*a0r - u10i*a0i + u11r*a1r - u11i*a1i;
                    aim[m1] = u10r*a0i + u10i*a0r + u11r*a1i + u11i*a1r;
                }
            }
        }
        #pragma unroll
        for (int q = 0; q < 4; q++) {
            unsigned shm  = 1u << (3 - q);
            unsigned cond = 1u << (4 - q);
            bool take = (lane & cond) != 0;
            #pragma unroll
            for (int m = 0; m < 8; m++) {
                float pr = __shfl_xor_sync(FULL, are[m], shm);
                float pi = __shfl_xor_sync(FULL, aim[m], shm);
                if (take) { are[m] = pr; aim[m] = pi; }
            }
        }
        if (lane & 1) {
            #pragma unroll
            for (int m = 0; m < 4; m++) {
                float tr = are[m]; are[m] = are[m+4]; are[m+4] = tr;
                float ti = aim[m]; aim[m] = aim[m+4]; aim[m+4] = ti;
            }
        }
        {
            float t;
            t = are[4]; are[4] = are[6]; are[6] = t;  t = aim[4]; aim[4] = aim[6]; aim[6] = t;
            t = are[5]; are[5] = are[7]; are[7] = t;  t = aim[5]; aim[5] = aim[7]; aim[7] = t;
            t = are[2]; are[2] = are[3]; are[3] = t;  t = aim[2]; aim[2] = aim[3]; aim[3] = t;
            t = are[6]; are[6] = are[7]; are[7] = t;  t = aim[6]; aim[6] = aim[7]; aim[7] = t;
        }
        #pragma unroll
        for (int m = 1; m < 8; m += 2) {
            are[m] = __shfl_xor_sync(FULL, are[m], 16);
            aim[m] = __shfl_xor_sync(FULL, aim[m], 16);
        }
    }

    float S = 0.f, S5 = 0.f, S6 = 0.f, S7 = 0.f;
    #pragma unroll
    for (int m = 0; m < 8; m++) {
        float p = are[m]*are[m] + aim[m]*aim[m];
        S  += p;
        S5 += (m & 4) ? -p : p;
        S6 += (m & 2) ? -p : p;
        S7 += (m & 1) ? -p : p;
    }
    float z[8];
    z[0] = (lane & 16) ? -S : S;
    z[1] = (lane &  8) ? -S : S;
    z[2] = (lane &  4) ? -S : S;
    z[3] = (lane &  2) ? -S : S;
    z[4] = (lane &  1) ? -S : S;
    z[5] = S5; z[6] = S6; z[7] = S7;
    #pragma unroll
    for (int q = 0; q < 8; q++)
        #pragma unroll
        for (int off = 16; off; off >>= 1)
            z[q] += __shfl_xor_sync(FULL, z[q], off);

    float in[14];
    #pragma unroll
    for (int k = 0; k < 8; k++) in[k] = z[k];
    #pragma unroll
    for (int k = 0; k < 6; k++) in[8 + k] = __ldg(scalars + (size_t)gs*6 + k);
    float acc = __ldg(hb1 + lane);
    #pragma unroll
    for (int k = 0; k < 14; k++) acc += in[k] * __ldg(hw1 + lane*14 + k);
    float bsc = __ldg(hg + lane) * rsqrtf(1.0f + 1e-5f);
    float h = fmaxf(acc*bsc + __ldg(hbb + lane), 0.f);
    #pragma unroll
    for (int o = 0; o < 3; o++) {
        float v = h * __ldg(hw2 + o*32 + lane);
        #pragma unroll
        for (int off = 16; off; off >>= 1) v += __shfl_xor_sync(FULL, v, off);
        if (lane == o) out[(size_t)gs*3 + o] = v + __ldg(hb2 + o);
    }
}

extern "C" void kernel_launch(void* const* d_in, const int* in_sizes, int n_in,
                              void* d_out, int out_size)
{
    const float* flux    = (const float*)d_in[0];
    const float* scalars = (const float*)d_in[1];
    const float* conv1_w = (const float*)d_in[2];
    const float* bn1_g   = (const float*)d_in[3];
    const float* bn1_b   = (const float*)d_in[4];
    const float* conv2_w = (const float*)d_in[5];
    const float* bn2_g   = (const float*)d_in[6];
    const float* bn2_b   = (const float*)d_in[7];
    const float* proj_w1 = (const float*)d_in[8];
    const float* proj_b1 = (const float*)d_in[9];
    const float* proj_w2 = (const float*)d_in[10];
    const float* proj_b2 = (const float*)d_in[11];
    const float* q_w     = (const float*)d_in[12];
    const float* head_w1 = (const float*)d_in[13];
    const float* head_b1 = (const float*)d_in[14];
    const float* head_g  = (const float*)d_in[15];
    const float* head_bb = (const float*)d_in[16];
    const float* head_w2 = (const float*)d_in[17];
    const float* head_b2 = (const float*)d_in[18];
    float* out = (float*)d_out;

    int B = in_sizes[1] / 6;           // scalars [B,6]
    if (B > BATCH) B = BATCH;

    cudaFuncSetAttribute(k_conv, cudaFuncAttributeMaxDynamicSharedMemorySize, SM1_TOTAL*4);
    cudaFuncSetAttribute(k_proj, cudaFuncAttributeMaxDynamicSharedMemorySize, SM2_TOTAL*4);

    k_conv<<<B, 256, SM1_TOTAL*4>>>(flux, conv1_w, bn1_g, bn1_b, conv2_w, bn2_g, bn2_b);
    k_proj<<<B/TB, 512, SM2_TOTAL*4>>>(proj_w1, proj_b1, proj_w2, proj_b2);
    k_circ<<<B/8, 256>>>(scalars, q_w, head_w1, head_b1, head_g, head_bb,
                         head_w2, head_b2, out);
}